// round 1
// baseline (speedup 1.0000x reference)
#include <cuda_runtime.h>

#define NGROUPS 4
#define COUNT   96
#define BATCH   8
#define IMG     224
#define NPIX    (IMG * IMG)
#define ACC_N   (NGROUPS * BATCH * COUNT)

// Persistent accumulators: [group][batch][channel]
__device__ float g_cnt[ACC_N];
__device__ float g_sum[ACC_N];
__device__ int   g_max[ACC_N];   // float bits; all values >= 0 so int compare == float compare

__global__ void zero_acc_kernel() {
    int i = blockIdx.x * blockDim.x + threadIdx.x;
    if (i < ACC_N) {
        g_cnt[i] = 0.0f;
        g_sum[i] = 0.0f;
        g_max[i] = 0;      // == 0.0f
    }
}

// Tile: 56 (x) by 32 (y) output pixels. 224 threads: 7 x-groups of 8 pixels, 32 rows.
template <int K>
__global__ __launch_bounds__(224)
void conv_pool_kernel(const float* __restrict__ X,
                      const float* __restrict__ W,
                      const float* __restrict__ Bv,
                      int group)
{
    constexpr int P   = (K - 1) / 2;
    constexpr int TX  = 56;
    constexpr int TY  = 32;
    constexpr int SW  = TX + K - 1;
    constexpr int SH  = TY + K - 1;
    constexpr int SWP = SW + 1;          // pad stride (odd) to decorrelate banks

    __shared__ float s_in[3 * SH * SWP];

    const int bx  = blockIdx.x;          // 0..3  (x tiles)
    const int by  = blockIdx.y;          // 0..6  (y tiles)
    const int bz  = blockIdx.z;          // batch*3 + channel-block
    const int b   = bz / 3;
    const int cb  = bz % 3;              // 32 output channels per block
    const int gx0 = bx * TX;
    const int gy0 = by * TY;
    const int tid = threadIdx.x;

    // Cooperative halo load (zero padding outside image).
    const float* Xb = X + (size_t)b * 3 * NPIX;
    for (int idx = tid; idx < 3 * SH * SW; idx += 224) {
        int ci = idx / (SH * SW);
        int r  = idx % (SH * SW);
        int sy = r / SW;
        int sx = r % SW;
        int iy = gy0 - P + sy;
        int ix = gx0 - P + sx;
        float v = 0.0f;
        if (iy >= 0 && iy < IMG && ix >= 0 && ix < IMG)
            v = Xb[(ci * IMG + iy) * IMG + ix];
        s_in[(ci * SH + sy) * SWP + sx] = v;
    }
    __syncthreads();

    const int ty = tid / 7;              // 0..31
    const int xb = (tid % 7) * 8;        // 0,8,...,48

    const int acc_base = (group * BATCH + b) * COUNT;

    for (int cpair = 0; cpair < 16; ++cpair) {
        const int oca = cb * 32 + cpair * 2;
        const int ocb = oca + 1;

        float accA[8], accB[8];
        #pragma unroll
        for (int j = 0; j < 8; ++j) { accA[j] = 0.0f; accB[j] = 0.0f; }

        #pragma unroll
        for (int ci = 0; ci < 3; ++ci) {
            #pragma unroll
            for (int dy = 0; dy < K; ++dy) {
                const float* rp = &s_in[(ci * SH + ty + dy) * SWP + xb];
                float win[K + 7];
                #pragma unroll
                for (int j = 0; j < K + 7; ++j) win[j] = rp[j];

                const float* wpA = &W[((oca * 3 + ci) * K + dy) * K];
                const float* wpB = &W[((ocb * 3 + ci) * K + dy) * K];
                #pragma unroll
                for (int dx = 0; dx < K; ++dx) {
                    const float wa = __ldg(wpA + dx);
                    const float wb = __ldg(wpB + dx);
                    #pragma unroll
                    for (int j = 0; j < 8; ++j) {
                        accA[j] = fmaf(wa, win[dx + j], accA[j]);
                        accB[j] = fmaf(wb, win[dx + j], accB[j]);
                    }
                }
            }
        }

        const float biasA = __ldg(Bv + oca);
        const float biasB = __ldg(Bv + ocb);

        // ---- channel A: bias + relu + local stats + warp reduce + atomics ----
        {
            float cnt = 0.0f, sum = 0.0f, mx = 0.0f;
            #pragma unroll
            for (int j = 0; j < 8; ++j) {
                float v = accA[j] + biasA;
                if (v > 0.0f) { cnt += 1.0f; sum += v; mx = fmaxf(mx, v); }
            }
            #pragma unroll
            for (int off = 16; off > 0; off >>= 1) {
                cnt += __shfl_down_sync(0xffffffffu, cnt, off);
                sum += __shfl_down_sync(0xffffffffu, sum, off);
                mx  = fmaxf(mx, __shfl_down_sync(0xffffffffu, mx, off));
            }
            if ((tid & 31) == 0) {
                int idx = acc_base + oca;
                atomicAdd(&g_cnt[idx], cnt);
                atomicAdd(&g_sum[idx], sum);
                atomicMax(&g_max[idx], __float_as_int(mx));
            }
        }
        // ---- channel B ----
        {
            float cnt = 0.0f, sum = 0.0f, mx = 0.0f;
            #pragma unroll
            for (int j = 0; j < 8; ++j) {
                float v = accB[j] + biasB;
                if (v > 0.0f) { cnt += 1.0f; sum += v; mx = fmaxf(mx, v); }
            }
            #pragma unroll
            for (int off = 16; off > 0; off >>= 1) {
                cnt += __shfl_down_sync(0xffffffffu, cnt, off);
                sum += __shfl_down_sync(0xffffffffu, sum, off);
                mx  = fmaxf(mx, __shfl_down_sync(0xffffffffu, mx, off));
            }
            if ((tid & 31) == 0) {
                int idx = acc_base + ocb;
                atomicAdd(&g_cnt[idx], cnt);
                atomicAdd(&g_sum[idx], sum);
                atomicMax(&g_max[idx], __float_as_int(mx));
            }
        }
    }
}

__global__ void finalize_kernel(float* __restrict__ out) {
    int i = blockIdx.x * blockDim.x + threadIdx.x;
    if (i >= ACC_N) return;
    int g = i / (BATCH * COUNT);
    int r = i % (BATCH * COUNT);
    int b = r / COUNT;
    int c = r % COUNT;

    float cnt = g_cnt[i];
    float sum = g_sum[i];
    float mx  = __int_as_float(g_max[i]);

    float ppv = cnt * (1.0f / (float)NPIX);
    float mpv = (cnt > 0.0f) ? (sum / cnt) : 0.0f;

    float* o = out + (size_t)b * (NGROUPS * 3 * COUNT) + g * (3 * COUNT);
    o[c]             = ppv;
    o[COUNT + c]     = mpv;
    o[2 * COUNT + c] = mx;
}

extern "C" void kernel_launch(void* const* d_in, const int* in_sizes, int n_in,
                              void* d_out, int out_size)
{
    const float* X  = (const float*)d_in[0];
    const float* w3 = (const float*)d_in[1];
    const float* b3 = (const float*)d_in[2];
    const float* w5 = (const float*)d_in[3];
    const float* b5 = (const float*)d_in[4];
    const float* w7 = (const float*)d_in[5];
    const float* b7 = (const float*)d_in[6];
    const float* w9 = (const float*)d_in[7];
    const float* b9 = (const float*)d_in[8];
    float* out = (float*)d_out;

    zero_acc_kernel<<<(ACC_N + 255) / 256, 256>>>();

    dim3 grid(4, 7, BATCH * 3);   // 4 x-tiles, 7 y-tiles, batch * channel-blocks
    conv_pool_kernel<3><<<grid, 224>>>(X, w3, b3, 0);
    conv_pool_kernel<5><<<grid, 224>>>(X, w5, b5, 1);
    conv_pool_kernel<7><<<grid, 224>>>(X, w7, b7, 2);
    conv_pool_kernel<9><<<grid, 224>>>(X, w9, b9, 3);

    finalize_kernel<<<(ACC_N + 255) / 256, 256>>>(out);
}